// round 3
// baseline (speedup 1.0000x reference)
#include <cuda_runtime.h>
#include <cstdint>

#define NB    16
#define NPTS  65536
#define NSEED 40
#define RAD2  0.0025f

#define FPS_CL 8
#define FPS_T  512
#define FPS_PT 16                // NPTS / (FPS_CL * FPS_T)
#define FPS_PR (FPS_PT / 2)

#define DEN_T      128
#define DEN_PT     16
#define DEN_CHUNKS (NPTS / (DEN_T * DEN_PT))   // 32

__device__ float g_seeds[NB * NSEED * 3];
__device__ float g_den[NB * NSEED];

// ---------------- f32x2 packed helpers (element-wise rn => bitwise == scalar)
__device__ __forceinline__ uint64_t pack2(float lo, float hi) {
    uint64_t r; asm("mov.b64 %0, {%1, %2};" : "=l"(r) : "f"(lo), "f"(hi)); return r;
}
__device__ __forceinline__ void unpack2(uint64_t v, float& lo, float& hi) {
    asm("mov.b64 {%0, %1}, %2;" : "=f"(lo), "=f"(hi) : "l"(v));
}
__device__ __forceinline__ uint64_t add2(uint64_t a, uint64_t b) {
    uint64_t r; asm("add.rn.f32x2 %0, %1, %2;" : "=l"(r) : "l"(a), "l"(b)); return r;
}
__device__ __forceinline__ uint64_t mul2(uint64_t a, uint64_t b) {
    uint64_t r; asm("mul.rn.f32x2 %0, %1, %2;" : "=l"(r) : "l"(a), "l"(b)); return r;
}
__device__ __forceinline__ uint64_t fma2(uint64_t a, uint64_t b, uint64_t c) {
    uint64_t r; asm("fma.rn.f32x2 %0, %1, %2, %3;" : "=l"(r) : "l"(a), "l"(b), "l"(c)); return r;
}

// ---------------- cluster / mbarrier helpers
__device__ __forceinline__ uint32_t ctarank() {
    uint32_t r; asm("mov.u32 %0, %%cluster_ctarank;" : "=r"(r)); return r;
}
__device__ __forceinline__ uint32_t mapa_u32(uint32_t sa, uint32_t rank) {
    uint32_t r; asm("mapa.shared::cluster.u32 %0, %1, %2;" : "=r"(r) : "r"(sa), "r"(rank));
    return r;
}
__device__ __forceinline__ void st_cluster_v4(uint32_t a, uint32_t x, uint32_t y,
                                              uint32_t z, uint32_t w) {
    asm volatile("st.shared::cluster.v4.b32 [%0], {%1,%2,%3,%4};"
                 :: "r"(a), "r"(x), "r"(y), "r"(z), "r"(w) : "memory");
}
__device__ __forceinline__ void st_cluster_b32(uint32_t a, uint32_t v) {
    asm volatile("st.shared::cluster.b32 [%0], %1;" :: "r"(a), "r"(v) : "memory");
}
__device__ __forceinline__ void mbar_init(uint32_t a, uint32_t cnt) {
    asm volatile("mbarrier.init.shared.b64 [%0], %1;" :: "r"(a), "r"(cnt) : "memory");
}
__device__ __forceinline__ void mbar_arrive_rel_cluster(uint32_t a) {
    asm volatile("mbarrier.arrive.release.cluster.shared::cluster.b64 _, [%0];"
                 :: "r"(a) : "memory");
}
__device__ __forceinline__ void mbar_wait_acq_cluster(uint32_t a, uint32_t parity) {
    asm volatile(
        "{\n\t.reg .pred P;\n\t"
        "WL_%=:\n\t"
        "mbarrier.try_wait.parity.acquire.cluster.shared::cta.b64 P, [%0], %1, 0x989680;\n\t"
        "@!P bra WL_%=;\n\t"
        "}" :: "r"(a), "r"(parity) : "memory");
}
__device__ __forceinline__ void cluster_sync_all() {
    asm volatile("barrier.cluster.arrive.aligned;" ::: "memory");
    asm volatile("barrier.cluster.wait.aligned;" ::: "memory");
}

// ---------------------------------------------------------------------------
// Kernel 1: farthest point sampling. 8-CTA cluster per batch; xyz packed
// f32x2 + u32 distance bits register-resident. Per step:
//   packed scan (fma pipe) with u32 min/max (alu pipe)
//   REDUX warp max -> lane0 smem atomicMax              -> bar
//   candidate thread: first-index via smem atomicMin    -> bar
//   candidate thread broadcasts (distbits, gi, xyz) to all 8 CTAs' slots via
//   st.shared::cluster + mbarrier arrive (payload straight from registers);
//   warp0 lane0 waits, serially reduces 8 slots (LDS, no shuffles), writes
//   s_cent                                              -> bar
// Tie-break: key (distbits<<32)|~gi, max => first global index == jnp.argmax.
// Distance math: mul/add rn in reference order ((dx^2+dy^2)+dz^2), bitexact.
// ---------------------------------------------------------------------------
__global__ void __cluster_dims__(FPS_CL, 1, 1) __launch_bounds__(FPS_T, 1)
fps_kernel(const float* __restrict__ pcs)
{
    const uint32_t rank = ctarank();
    const int batch = blockIdx.x / FPS_CL;
    const int t = threadIdx.x;
    const int lane = t & 31;

    __shared__ unsigned s_best[2];
    __shared__ unsigned s_idx[2];
    __shared__ float s_cent[3];
    __shared__ __align__(16) uint4 s_slot4[2][FPS_CL];   // {distbits, gi, xbits, ybits}
    __shared__ float s_slotz[2][FPS_CL];
    __shared__ __align__(8) unsigned long long s_mbar[2];

    const float* base = pcs + (size_t)batch * NPTS * 3;
    const int gi0 = (int)rank * (FPS_T * FPS_PT) + t;

    // ---- load points, pack pairs (2j, 2j+1)
    uint64_t PX[FPS_PR], PY[FPS_PR], PZ[FPS_PR];
#pragma unroll
    for (int j = 0; j < FPS_PR; j++) {
        const int ga = gi0 + (2 * j) * FPS_T;
        const int gb = gi0 + (2 * j + 1) * FPS_T;
        PX[j] = pack2(base[ga * 3 + 0], base[gb * 3 + 0]);
        PY[j] = pack2(base[ga * 3 + 1], base[gb * 3 + 1]);
        PZ[j] = pack2(base[ga * 3 + 2], base[gb * 3 + 2]);
    }
    unsigned db[FPS_PT];
#pragma unroll
    for (int i = 0; i < FPS_PT; i++) db[i] = __float_as_uint(1e10f);

    if (t == 0) {
        mbar_init((uint32_t)__cvta_generic_to_shared(&s_mbar[0]), FPS_CL);
        mbar_init((uint32_t)__cvta_generic_to_shared(&s_mbar[1]), FPS_CL);
        s_cent[0] = base[0]; s_cent[1] = base[1]; s_cent[2] = base[2];
        s_best[0] = 0;            s_best[1] = 0;
        s_idx[0] = 0xffffffffu;   s_idx[1] = 0xffffffffu;
    }
    if (rank == 0) {
        if (t < NSEED) g_den[batch * NSEED + t] = 0.0f;
        if (t == 0) {
            g_seeds[(batch * NSEED) * 3 + 0] = base[0];
            g_seeds[(batch * NSEED) * 3 + 1] = base[1];
            g_seeds[(batch * NSEED) * 3 + 2] = base[2];
        }
    }
    __syncthreads();
    cluster_sync_all();   // all mbarriers initialized cluster-wide

#pragma unroll 1
    for (int k = 0; k < NSEED - 1; k++) {
        const int b = k & 1;
        const float cx = s_cent[0], cy = s_cent[1], cz = s_cent[2];
        const uint64_t ncx2 = pack2(-cx, -cx);
        const uint64_t ncy2 = pack2(-cy, -cy);
        const uint64_t ncz2 = pack2(-cz, -cz);

        // ---- packed scan; two max accumulators for ILP
        unsigned bd0 = 0, bd1 = 0;
#pragma unroll
        for (int j = 0; j < FPS_PR; j++) {
            const uint64_t ax = add2(PX[j], ncx2);
            const uint64_t ay = add2(PY[j], ncy2);
            const uint64_t az = add2(PZ[j], ncz2);
            const uint64_t dd = add2(add2(mul2(ax, ax), mul2(ay, ay)), mul2(az, az));
            float f0, f1; unpack2(dd, f0, f1);
            const unsigned u0 = __float_as_uint(f0);
            const unsigned u1 = __float_as_uint(f1);
            db[2 * j]     = min(db[2 * j],     u0);
            db[2 * j + 1] = min(db[2 * j + 1], u1);
            bd0 = max(bd0, db[2 * j]);
            bd1 = max(bd1, db[2 * j + 1]);
        }
        const unsigned bd = max(bd0, bd1);

        // ---- warp max (single REDUX) -> block max via one smem atomic
        const unsigned wbd = __reduce_max_sync(0xffffffffu, bd);
        if (lane == 0) atomicMax(&s_best[b], wbd);
        if (t == 0) {                       // reset other buffer (unused this step)
            s_best[b ^ 1] = 0;
            s_idx[b ^ 1] = 0xffffffffu;
        }
        __syncthreads();

        const unsigned best = s_best[b];
        unsigned mygi = 0xffffffffu;
        if (bd == best) {                   // rare: candidate thread(s)
#pragma unroll
            for (int i = 0; i < FPS_PT; i++)
                if (db[i] == best) mygi = min(mygi, (unsigned)(gi0 + i * FPS_T));
            atomicMin(&s_idx[b], mygi);
        }
        __syncthreads();

        const unsigned widx = s_idx[b];

        // ---- unique winner thread broadcasts payload to all 8 CTAs
        if (bd == best && mygi == widx) {
            const int i = (int)(widx - (unsigned)gi0) / FPS_T;
            float x0, x1, y0, y1, z0, z1;
            unpack2(PX[i >> 1], x0, x1);
            unpack2(PY[i >> 1], y0, y1);
            unpack2(PZ[i >> 1], z0, z1);
            const unsigned xb = __float_as_uint((i & 1) ? x1 : x0);
            const unsigned yb = __float_as_uint((i & 1) ? y1 : y0);
            const unsigned zb = __float_as_uint((i & 1) ? z1 : z0);
            const uint32_t slot_loc = (uint32_t)__cvta_generic_to_shared(&s_slot4[b][rank]);
            const uint32_t z_loc    = (uint32_t)__cvta_generic_to_shared(&s_slotz[b][rank]);
            const uint32_t bar_loc  = (uint32_t)__cvta_generic_to_shared(&s_mbar[b]);
#pragma unroll
            for (uint32_t r = 0; r < FPS_CL; r++) {
                st_cluster_v4(mapa_u32(slot_loc, r), best, widx, xb, yb);
                st_cluster_b32(mapa_u32(z_loc, r), zb);
                mbar_arrive_rel_cluster(mapa_u32(bar_loc, r));
            }
        }

        // ---- warp0 lane0: wait for all 8 CTAs, serial reduce, publish cent
        if (t == 0) {
            mbar_wait_acq_cluster((uint32_t)__cvta_generic_to_shared(&s_mbar[b]),
                                  (unsigned)((k >> 1) & 1));
            unsigned long long bk = 0;
            float wx = 0.f, wy = 0.f, wz = 0.f;
#pragma unroll
            for (int r = 0; r < FPS_CL; r++) {
                const uint4 sl = s_slot4[b][r];
                const float slz = s_slotz[b][r];
                const unsigned long long key =
                    ((unsigned long long)sl.x << 32) | (unsigned)(~sl.y);
                if (key > bk) {
                    bk = key;
                    wx = __uint_as_float(sl.z);
                    wy = __uint_as_float(sl.w);
                    wz = slz;
                }
            }
            s_cent[0] = wx; s_cent[1] = wy; s_cent[2] = wz;
            if (rank == 0) {
                float* gs = &g_seeds[(batch * NSEED + k + 1) * 3];
                gs[0] = wx; gs[1] = wy; gs[2] = wz;
            }
        }
        __syncthreads();
    }
    cluster_sync_all();
}

// ---------------------------------------------------------------------------
// Kernel 2: den[b][s] = sum_n relu(r^2 - (|s|^2 + |p|^2 - 2 s.p))
// ---------------------------------------------------------------------------
__global__ void __launch_bounds__(DEN_T)
den_kernel(const float* __restrict__ pcs)
{
    const int batch = blockIdx.y;
    const int chunk = blockIdx.x;
    const int t = threadIdx.x;

    __shared__ float4 ss[NSEED];
    if (t < NSEED) {
        const float* gs = &g_seeds[(batch * NSEED + t) * 3];
        const float sx = gs[0], sy = gs[1], sz = gs[2];
        const float sn = sx * sx + sy * sy + sz * sz;
        ss[t] = make_float4(2.0f * sx, 2.0f * sy, 2.0f * sz, RAD2 - sn);
    }
    __syncthreads();

    const float* base = pcs + (size_t)batch * NPTS * 3;
    const int p0 = chunk * (DEN_T * DEN_PT) + t;

    uint64_t X2[DEN_PT / 2], Y2[DEN_PT / 2], Z2[DEN_PT / 2], NPN2[DEN_PT / 2];
#pragma unroll
    for (int j = 0; j < DEN_PT / 2; j++) {
        const int g0 = p0 + (2 * j) * DEN_T;
        const int g1 = p0 + (2 * j + 1) * DEN_T;
        const float x0 = base[g0 * 3 + 0], y0 = base[g0 * 3 + 1], z0 = base[g0 * 3 + 2];
        const float x1 = base[g1 * 3 + 0], y1 = base[g1 * 3 + 1], z1 = base[g1 * 3 + 2];
        X2[j] = pack2(x0, x1);
        Y2[j] = pack2(y0, y1);
        Z2[j] = pack2(z0, z1);
        const float pn0 = fmaf(z0, z0, fmaf(y0, y0, x0 * x0));
        const float pn1 = fmaf(z1, z1, fmaf(y1, y1, x1 * x1));
        NPN2[j] = pack2(-pn0, -pn1);
    }

#pragma unroll 1
    for (int s = 0; s < NSEED; s++) {
        const float4 q = ss[s];
        const uint64_t qx2 = pack2(q.x, q.x);
        const uint64_t qy2 = pack2(q.y, q.y);
        const uint64_t qz2 = pack2(q.z, q.z);
        const uint64_t qw2 = pack2(q.w, q.w);
        float acc = 0.0f;
#pragma unroll
        for (int j = 0; j < DEN_PT / 2; j++) {
            uint64_t v = add2(qw2, NPN2[j]);
            v = fma2(X2[j], qx2, v);
            v = fma2(Y2[j], qy2, v);
            v = fma2(Z2[j], qz2, v);
            float v0, v1; unpack2(v, v0, v1);
            acc += fmaxf(v0, 0.0f);
            acc += fmaxf(v1, 0.0f);
        }
        if (acc != 0.0f) atomicAdd(&g_den[batch * NSEED + s], acc);
    }
}

// ---------------------------------------------------------------------------
// Kernel 3: out = mean_b( var_{ddof=1,s}( den[b][s] ) )
// ---------------------------------------------------------------------------
__global__ void var_kernel(float* __restrict__ out)
{
    const int lane = threadIdx.x;
    float v = 0.0f;
    if (lane < NB) {
        const float* d = &g_den[lane * NSEED];
        float s = 0.0f;
        for (int i = 0; i < NSEED; i++) s += d[i];
        const float m = s * (1.0f / NSEED);
        float q = 0.0f;
        for (int i = 0; i < NSEED; i++) {
            const float e = d[i] - m;
            q += e * e;
        }
        v = q * (1.0f / (NSEED - 1));
    }
#pragma unroll
    for (int off = 8; off; off >>= 1)
        v += __shfl_down_sync(0xffffffffu, v, off);
    if (lane == 0) out[0] = v * (1.0f / NB);
}

// ---------------------------------------------------------------------------
extern "C" void kernel_launch(void* const* d_in, const int* in_sizes, int n_in,
                              void* d_out, int out_size)
{
    const float* pcs = (const float*)d_in[0];
    (void)in_sizes; (void)n_in; (void)out_size;

    fps_kernel<<<NB * FPS_CL, FPS_T>>>(pcs);
    den_kernel<<<dim3(DEN_CHUNKS, NB), DEN_T>>>(pcs);
    var_kernel<<<1, 32>>>((float*)d_out);
}

// round 4
// speedup vs baseline: 1.5182x; 1.5182x over previous
#include <cuda_runtime.h>
#include <cstdint>

#define NB    16
#define NPTS  65536
#define NSEED 40
#define RAD2  0.0025f

#define FPS_CL 8
#define FPS_T  1024
#define FPS_PT 8                 // NPTS / (FPS_CL * FPS_T)
#define FPS_PR (FPS_PT / 2)

#define DEN_T      128
#define DEN_PT     16
#define DEN_CHUNKS (NPTS / (DEN_T * DEN_PT))   // 32

__device__ float g_seeds[NB * NSEED * 3];
__device__ float g_den[NB * NSEED];

// ---------------- f32x2 packed helpers (element-wise rn => bitwise == scalar)
__device__ __forceinline__ uint64_t pack2(float lo, float hi) {
    uint64_t r; asm("mov.b64 %0, {%1, %2};" : "=l"(r) : "f"(lo), "f"(hi)); return r;
}
__device__ __forceinline__ void unpack2(uint64_t v, float& lo, float& hi) {
    asm("mov.b64 {%0, %1}, %2;" : "=f"(lo), "=f"(hi) : "l"(v));
}
__device__ __forceinline__ uint64_t add2(uint64_t a, uint64_t b) {
    uint64_t r; asm("add.rn.f32x2 %0, %1, %2;" : "=l"(r) : "l"(a), "l"(b)); return r;
}
__device__ __forceinline__ uint64_t mul2(uint64_t a, uint64_t b) {
    uint64_t r; asm("mul.rn.f32x2 %0, %1, %2;" : "=l"(r) : "l"(a), "l"(b)); return r;
}
__device__ __forceinline__ uint64_t fma2(uint64_t a, uint64_t b, uint64_t c) {
    uint64_t r; asm("fma.rn.f32x2 %0, %1, %2, %3;" : "=l"(r) : "l"(a), "l"(b), "l"(c)); return r;
}

// ---------------- cluster / mbarrier helpers
__device__ __forceinline__ uint32_t ctarank() {
    uint32_t r; asm("mov.u32 %0, %%cluster_ctarank;" : "=r"(r)); return r;
}
__device__ __forceinline__ uint32_t mapa_u32(uint32_t sa, uint32_t rank) {
    uint32_t r; asm("mapa.shared::cluster.u32 %0, %1, %2;" : "=r"(r) : "r"(sa), "r"(rank));
    return r;
}
__device__ __forceinline__ void st_cluster_v4(uint32_t a, uint32_t x, uint32_t y,
                                              uint32_t z, uint32_t w) {
    asm volatile("st.shared::cluster.v4.b32 [%0], {%1,%2,%3,%4};"
                 :: "r"(a), "r"(x), "r"(y), "r"(z), "r"(w) : "memory");
}
__device__ __forceinline__ void st_cluster_b32(uint32_t a, uint32_t v) {
    asm volatile("st.shared::cluster.b32 [%0], %1;" :: "r"(a), "r"(v) : "memory");
}
__device__ __forceinline__ void mbar_init(uint32_t a, uint32_t cnt) {
    asm volatile("mbarrier.init.shared.b64 [%0], %1;" :: "r"(a), "r"(cnt) : "memory");
}
__device__ __forceinline__ void mbar_arrive_rel_cluster(uint32_t a) {
    asm volatile("mbarrier.arrive.release.cluster.shared::cluster.b64 _, [%0];"
                 :: "r"(a) : "memory");
}
__device__ __forceinline__ void mbar_wait_acq_cluster(uint32_t a, uint32_t parity) {
    asm volatile(
        "{\n\t.reg .pred P;\n\t"
        "WL_%=:\n\t"
        "mbarrier.try_wait.parity.acquire.cluster.shared::cta.b64 P, [%0], %1, 0x989680;\n\t"
        "@!P bra WL_%=;\n\t"
        "}" :: "r"(a), "r"(parity) : "memory");
}
__device__ __forceinline__ void cluster_sync_all() {
    asm volatile("barrier.cluster.arrive.aligned;" ::: "memory");
    asm volatile("barrier.cluster.wait.aligned;" ::: "memory");
}

// ---------------------------------------------------------------------------
// Kernel 1: farthest point sampling. 8-CTA cluster per batch; xyz packed f32x2
// and u32 distance bits register-resident. Per step (2 barriers total):
//   packed scan (fma pipe) with u32 min/max (alu pipe)
//   REDUX max(distbits) + REDUX min(candidate gi) -> lane0 u64 atomicMax of
//     key {distbits<<32 | ~gi} into s_key[b]            -> bar1
//   owner warp (contains thread widx&1023): shuffle xyz out of owner regs,
//     lanes 0..7 store {key payload} to all 8 CTAs' slots + arrive (parallel)
//   t0: mbar wait (acquire), serial 8-slot reduce, s_cent -> bar2
// Tie-break: max key => max dist, then FIRST global index == jnp.argmax.
// Distance math: mul/add rn in reference order ((dx^2+dy^2)+dz^2), bitexact.
// ---------------------------------------------------------------------------
__global__ void __cluster_dims__(FPS_CL, 1, 1) __launch_bounds__(FPS_T, 1)
fps_kernel(const float* __restrict__ pcs)
{
    const uint32_t rank = ctarank();
    const int batch = blockIdx.x / FPS_CL;
    const int t = threadIdx.x;
    const int lane = t & 31;
    const int warp = t >> 5;

    __shared__ unsigned long long s_key[2];
    __shared__ float s_cent[3];
    __shared__ __align__(16) uint4 s_slot4[2][FPS_CL];   // {distbits, gi, xbits, ybits}
    __shared__ float s_slotz[2][FPS_CL];
    __shared__ __align__(8) unsigned long long s_mbar[2];

    const float* base = pcs + (size_t)batch * NPTS * 3;
    const int gi0 = (int)rank * (FPS_T * FPS_PT) + t;

    // ---- load points, pack pairs (2j, 2j+1)
    uint64_t PX[FPS_PR], PY[FPS_PR], PZ[FPS_PR];
#pragma unroll
    for (int j = 0; j < FPS_PR; j++) {
        const int ga = gi0 + (2 * j) * FPS_T;
        const int gb = gi0 + (2 * j + 1) * FPS_T;
        PX[j] = pack2(base[ga * 3 + 0], base[gb * 3 + 0]);
        PY[j] = pack2(base[ga * 3 + 1], base[gb * 3 + 1]);
        PZ[j] = pack2(base[ga * 3 + 2], base[gb * 3 + 2]);
    }
    unsigned db[FPS_PT];
#pragma unroll
    for (int i = 0; i < FPS_PT; i++) db[i] = __float_as_uint(1e10f);

    if (t == 0) {
        mbar_init((uint32_t)__cvta_generic_to_shared(&s_mbar[0]), FPS_CL);
        mbar_init((uint32_t)__cvta_generic_to_shared(&s_mbar[1]), FPS_CL);
        s_cent[0] = base[0]; s_cent[1] = base[1]; s_cent[2] = base[2];
        s_key[0] = 0; s_key[1] = 0;
    }
    if (rank == 0) {
        if (t < NSEED) g_den[batch * NSEED + t] = 0.0f;
        if (t == 0) {
            g_seeds[(batch * NSEED) * 3 + 0] = base[0];
            g_seeds[(batch * NSEED) * 3 + 1] = base[1];
            g_seeds[(batch * NSEED) * 3 + 2] = base[2];
        }
    }
    __syncthreads();
    cluster_sync_all();   // mbarriers initialized cluster-wide

#pragma unroll 1
    for (int k = 0; k < NSEED - 1; k++) {
        const int b = k & 1;
        const float cx = s_cent[0], cy = s_cent[1], cz = s_cent[2];
        const uint64_t ncx2 = pack2(-cx, -cx);
        const uint64_t ncy2 = pack2(-cy, -cy);
        const uint64_t ncz2 = pack2(-cz, -cz);

        // ---- packed scan; two max accumulators for ILP
        unsigned bd0 = 0, bd1 = 0;
#pragma unroll
        for (int j = 0; j < FPS_PR; j++) {
            const uint64_t ax = add2(PX[j], ncx2);
            const uint64_t ay = add2(PY[j], ncy2);
            const uint64_t az = add2(PZ[j], ncz2);
            const uint64_t dd = add2(add2(mul2(ax, ax), mul2(ay, ay)), mul2(az, az));
            float f0, f1; unpack2(dd, f0, f1);
            db[2 * j]     = min(db[2 * j],     __float_as_uint(f0));
            db[2 * j + 1] = min(db[2 * j + 1], __float_as_uint(f1));
            bd0 = max(bd0, db[2 * j]);
            bd1 = max(bd1, db[2 * j + 1]);
        }
        const unsigned bd = max(bd0, bd1);

        // ---- warp REDUX max + candidate first-gi REDUX min, one smem atomic
        const unsigned wbd = __reduce_max_sync(0xffffffffu, bd);
        unsigned mygi = 0xffffffffu;
        if (bd == wbd) {
#pragma unroll
            for (int i = 0; i < FPS_PT; i++)
                if (db[i] == wbd) mygi = min(mygi, (unsigned)(gi0 + i * FPS_T));
        }
        const unsigned wgi = __reduce_min_sync(0xffffffffu, mygi);
        if (lane == 0) {
            const unsigned long long key =
                ((unsigned long long)wbd << 32) | (unsigned)(~wgi);
            atomicMax(&s_key[b], key);
        }
        if (t == 0) s_key[b ^ 1] = 0;     // reset idle buffer for next step
        __syncthreads();                  // ---- bar1: CTA winner final

        const unsigned long long ckey = s_key[b];
        const unsigned widx = ~(unsigned)(ckey & 0xffffffffull);
        const unsigned best = (unsigned)(ckey >> 32);
        const int owner_t = (int)(widx & (FPS_T - 1));

        // ---- owner warp: extract xyz from owner regs, 8 lanes broadcast
        if (warp == (owner_t >> 5)) {
            const int oi = (int)((widx >> 10) & (FPS_PT - 1));
            float ox = 0.f, oy = 0.f, oz = 0.f;
#pragma unroll
            for (int i = 0; i < FPS_PT; i++) {
                if (i == oi) {
                    float a0, a1;
                    unpack2(PX[i >> 1], a0, a1); ox = (i & 1) ? a1 : a0;
                    unpack2(PY[i >> 1], a0, a1); oy = (i & 1) ? a1 : a0;
                    unpack2(PZ[i >> 1], a0, a1); oz = (i & 1) ? a1 : a0;
                }
            }
            const int src = owner_t & 31;
            const unsigned xb = __float_as_uint(__shfl_sync(0xffffffffu, ox, src));
            const unsigned yb = __float_as_uint(__shfl_sync(0xffffffffu, oy, src));
            const unsigned zb = __float_as_uint(__shfl_sync(0xffffffffu, oz, src));
            if (lane < FPS_CL) {
                const uint32_t slot_loc =
                    (uint32_t)__cvta_generic_to_shared(&s_slot4[b][rank]);
                const uint32_t z_loc =
                    (uint32_t)__cvta_generic_to_shared(&s_slotz[b][rank]);
                const uint32_t bar_loc =
                    (uint32_t)__cvta_generic_to_shared(&s_mbar[b]);
                st_cluster_v4(mapa_u32(slot_loc, (uint32_t)lane), best, widx, xb, yb);
                st_cluster_b32(mapa_u32(z_loc, (uint32_t)lane), zb);
                mbar_arrive_rel_cluster(mapa_u32(bar_loc, (uint32_t)lane));
            }
        }

        // ---- t0: wait all 8 CTAs, serial slot reduce, publish centroid
        if (t == 0) {
            mbar_wait_acq_cluster((uint32_t)__cvta_generic_to_shared(&s_mbar[b]),
                                  (unsigned)((k >> 1) & 1));
            unsigned long long bk = 0;
            float wx = 0.f, wy = 0.f, wz = 0.f;
#pragma unroll
            for (int r = 0; r < FPS_CL; r++) {
                const uint4 sl = s_slot4[b][r];
                const float slz = s_slotz[b][r];
                const unsigned long long key =
                    ((unsigned long long)sl.x << 32) | (unsigned)(~sl.y);
                if (key > bk) {
                    bk = key;
                    wx = __uint_as_float(sl.z);
                    wy = __uint_as_float(sl.w);
                    wz = slz;
                }
            }
            s_cent[0] = wx; s_cent[1] = wy; s_cent[2] = wz;
            if (rank == 0) {
                float* gs = &g_seeds[(batch * NSEED + k + 1) * 3];
                gs[0] = wx; gs[1] = wy; gs[2] = wz;
            }
        }
        __syncthreads();                  // ---- bar2: centroid published
    }
    cluster_sync_all();
}

// ---------------------------------------------------------------------------
// Kernel 2: den[b][s] = sum_n relu(r^2 - (|s|^2 + |p|^2 - 2 s.p))
// ---------------------------------------------------------------------------
__global__ void __launch_bounds__(DEN_T)
den_kernel(const float* __restrict__ pcs)
{
    const int batch = blockIdx.y;
    const int chunk = blockIdx.x;
    const int t = threadIdx.x;

    __shared__ float4 ss[NSEED];
    if (t < NSEED) {
        const float* gs = &g_seeds[(batch * NSEED + t) * 3];
        const float sx = gs[0], sy = gs[1], sz = gs[2];
        const float sn = sx * sx + sy * sy + sz * sz;
        ss[t] = make_float4(2.0f * sx, 2.0f * sy, 2.0f * sz, RAD2 - sn);
    }
    __syncthreads();

    const float* base = pcs + (size_t)batch * NPTS * 3;
    const int p0 = chunk * (DEN_T * DEN_PT) + t;

    uint64_t X2[DEN_PT / 2], Y2[DEN_PT / 2], Z2[DEN_PT / 2], NPN2[DEN_PT / 2];
#pragma unroll
    for (int j = 0; j < DEN_PT / 2; j++) {
        const int g0 = p0 + (2 * j) * DEN_T;
        const int g1 = p0 + (2 * j + 1) * DEN_T;
        const float x0 = base[g0 * 3 + 0], y0 = base[g0 * 3 + 1], z0 = base[g0 * 3 + 2];
        const float x1 = base[g1 * 3 + 0], y1 = base[g1 * 3 + 1], z1 = base[g1 * 3 + 2];
        X2[j] = pack2(x0, x1);
        Y2[j] = pack2(y0, y1);
        Z2[j] = pack2(z0, z1);
        const float pn0 = fmaf(z0, z0, fmaf(y0, y0, x0 * x0));
        const float pn1 = fmaf(z1, z1, fmaf(y1, y1, x1 * x1));
        NPN2[j] = pack2(-pn0, -pn1);
    }

#pragma unroll 1
    for (int s = 0; s < NSEED; s++) {
        const float4 q = ss[s];
        const uint64_t qx2 = pack2(q.x, q.x);
        const uint64_t qy2 = pack2(q.y, q.y);
        const uint64_t qz2 = pack2(q.z, q.z);
        const uint64_t qw2 = pack2(q.w, q.w);
        float acc = 0.0f;
#pragma unroll
        for (int j = 0; j < DEN_PT / 2; j++) {
            uint64_t v = add2(qw2, NPN2[j]);
            v = fma2(X2[j], qx2, v);
            v = fma2(Y2[j], qy2, v);
            v = fma2(Z2[j], qz2, v);
            float v0, v1; unpack2(v, v0, v1);
            acc += fmaxf(v0, 0.0f);
            acc += fmaxf(v1, 0.0f);
        }
        if (acc != 0.0f) atomicAdd(&g_den[batch * NSEED + s], acc);
    }
}

// ---------------------------------------------------------------------------
// Kernel 3: out = mean_b( var_{ddof=1,s}( den[b][s] ) )
// ---------------------------------------------------------------------------
__global__ void var_kernel(float* __restrict__ out)
{
    const int lane = threadIdx.x;
    float v = 0.0f;
    if (lane < NB) {
        const float* d = &g_den[lane * NSEED];
        float s = 0.0f;
        for (int i = 0; i < NSEED; i++) s += d[i];
        const float m = s * (1.0f / NSEED);
        float q = 0.0f;
        for (int i = 0; i < NSEED; i++) {
            const float e = d[i] - m;
            q += e * e;
        }
        v = q * (1.0f / (NSEED - 1));
    }
#pragma unroll
    for (int off = 8; off; off >>= 1)
        v += __shfl_down_sync(0xffffffffu, v, off);
    if (lane == 0) out[0] = v * (1.0f / NB);
}

// ---------------------------------------------------------------------------
extern "C" void kernel_launch(void* const* d_in, const int* in_sizes, int n_in,
                              void* d_out, int out_size)
{
    const float* pcs = (const float*)d_in[0];
    (void)in_sizes; (void)n_in; (void)out_size;

    fps_kernel<<<NB * FPS_CL, FPS_T>>>(pcs);
    den_kernel<<<dim3(DEN_CHUNKS, NB), DEN_T>>>(pcs);
    var_kernel<<<1, 32>>>((float*)d_out);
}

// round 5
// speedup vs baseline: 1.6762x; 1.1041x over previous
#include <cuda_runtime.h>
#include <cstdint>

#define NB    16
#define NPTS  65536
#define NSEED 40
#define RAD2  0.0025f

#define FPS_CL 8
#define FPS_T  256
#define FPS_PT 32                // NPTS / (FPS_CL * FPS_T)
#define FPS_PR (FPS_PT / 2)

__device__ float g_den[NB * NSEED];

// ---------------- f32x2 packed helpers (element-wise rn => bitwise == scalar)
__device__ __forceinline__ uint64_t pack2(float lo, float hi) {
    uint64_t r; asm("mov.b64 %0, {%1, %2};" : "=l"(r) : "f"(lo), "f"(hi)); return r;
}
__device__ __forceinline__ void unpack2(uint64_t v, float& lo, float& hi) {
    asm("mov.b64 {%0, %1}, %2;" : "=f"(lo), "=f"(hi) : "l"(v));
}
__device__ __forceinline__ uint64_t add2(uint64_t a, uint64_t b) {
    uint64_t r; asm("add.rn.f32x2 %0, %1, %2;" : "=l"(r) : "l"(a), "l"(b)); return r;
}
__device__ __forceinline__ uint64_t mul2(uint64_t a, uint64_t b) {
    uint64_t r; asm("mul.rn.f32x2 %0, %1, %2;" : "=l"(r) : "l"(a), "l"(b)); return r;
}
__device__ __forceinline__ uint64_t fma2(uint64_t a, uint64_t b, uint64_t c) {
    uint64_t r; asm("fma.rn.f32x2 %0, %1, %2, %3;" : "=l"(r) : "l"(a), "l"(b), "l"(c)); return r;
}

// ---------------- cluster / mbarrier helpers
__device__ __forceinline__ uint32_t ctarank() {
    uint32_t r; asm("mov.u32 %0, %%cluster_ctarank;" : "=r"(r)); return r;
}
__device__ __forceinline__ uint32_t mapa_u32(uint32_t sa, uint32_t rank) {
    uint32_t r; asm("mapa.shared::cluster.u32 %0, %1, %2;" : "=r"(r) : "r"(sa), "r"(rank));
    return r;
}
__device__ __forceinline__ void st_cluster_b64(uint32_t a, uint64_t v) {
    asm volatile("st.shared::cluster.b64 [%0], %1;" :: "r"(a), "l"(v) : "memory");
}
__device__ __forceinline__ void mbar_init(uint32_t a, uint32_t cnt) {
    asm volatile("mbarrier.init.shared.b64 [%0], %1;" :: "r"(a), "r"(cnt) : "memory");
}
__device__ __forceinline__ void mbar_arrive_rel_cluster(uint32_t a) {
    asm volatile("mbarrier.arrive.release.cluster.shared::cluster.b64 _, [%0];"
                 :: "r"(a) : "memory");
}
__device__ __forceinline__ void mbar_wait_acq_cluster(uint32_t a, uint32_t parity) {
    asm volatile(
        "{\n\t.reg .pred P;\n\t"
        "WL_%=:\n\t"
        "mbarrier.try_wait.parity.acquire.cluster.shared::cta.b64 P, [%0], %1, 0x989680;\n\t"
        "@!P bra WL_%=;\n\t"
        "}" :: "r"(a), "r"(parity) : "memory");
}
__device__ __forceinline__ void cluster_sync_all() {
    asm volatile("barrier.cluster.arrive.aligned;" ::: "memory");
    asm volatile("barrier.cluster.wait.aligned;" ::: "memory");
}

// ---------------------------------------------------------------------------
// Kernel 1: FPS + density, fused. 8-CTA cluster per batch, 256 thr/CTA,
// 32 pts/thread register-resident (packed f32x2). Per FPS step (2 barriers,
// no atomics):
//   packed scan -> per-thread max distbits (u32, IEEE order == int order)
//   warp: REDUX max(distbits); candidates rescan for first gi; REDUX min(gi);
//         lane0 STS u64 key {distbits<<32 | ~gi} to s_wkey[warp]   -> bar1
//   warp0: 8-key dual-REDUX -> lanes 0..7 st.shared::cluster key to all CTAs
//          + mbarrier arrive (parallel); all lanes wait; 8-slot dual-REDUX;
//          lanes 0..2 LDG winner xyz -> s_seeds[k+1]                -> bar2
// Tie-break: max key => max dist then FIRST global index == jnp.argmax.
// Distance math: mul/add rn in reference order ((dx^2+dy^2)+dz^2), bitexact.
// Then density tail: 40-seed packed-FMA sweep over the register-resident
// points, per-thread partials -> smem -> 40 column sums -> global atomicAdd.
// ---------------------------------------------------------------------------
__global__ void __cluster_dims__(FPS_CL, 1, 1) __launch_bounds__(FPS_T, 1)
fps_kernel(const float* __restrict__ pcs)
{
    const uint32_t rank = ctarank();
    const int batch = blockIdx.x / FPS_CL;
    const int t = threadIdx.x;
    const int lane = t & 31;
    const int warp = t >> 5;

    __shared__ uint64_t s_wkey[FPS_T / 32];          // 8 per-warp keys
    __shared__ __align__(16) float s_seeds[NSEED][4];
    __shared__ uint64_t s_slot[2][FPS_CL];
    __shared__ __align__(8) unsigned long long s_mbar[2];
    __shared__ float s_part[NSEED][FPS_T + 1];       // den partials (41.1 KB)

    const float* base = pcs + (size_t)batch * NPTS * 3;
    const int gi0 = (int)rank * (FPS_T * FPS_PT) + t;

    // ---- load 32 points, pack pairs (2j, 2j+1)
    uint64_t PX[FPS_PR], PY[FPS_PR], PZ[FPS_PR];
#pragma unroll
    for (int j = 0; j < FPS_PR; j++) {
        const int ga = gi0 + (2 * j) * FPS_T;
        const int gb = gi0 + (2 * j + 1) * FPS_T;
        PX[j] = pack2(base[ga * 3 + 0], base[gb * 3 + 0]);
        PY[j] = pack2(base[ga * 3 + 1], base[gb * 3 + 1]);
        PZ[j] = pack2(base[ga * 3 + 2], base[gb * 3 + 2]);
    }
    unsigned db[FPS_PT];
#pragma unroll
    for (int i = 0; i < FPS_PT; i++) db[i] = __float_as_uint(1e10f);

    if (t == 0) {
        mbar_init((uint32_t)__cvta_generic_to_shared(&s_mbar[0]), FPS_CL);
        mbar_init((uint32_t)__cvta_generic_to_shared(&s_mbar[1]), FPS_CL);
    }
    if (t < 3) s_seeds[0][t] = base[t];
    if (rank == 0 && t < NSEED) g_den[batch * NSEED + t] = 0.0f;
    __syncthreads();
    cluster_sync_all();   // mbarriers initialized cluster-wide

    // =================== FPS main loop ===================
#pragma unroll 1
    for (int k = 0; k < NSEED - 1; k++) {
        const int b = k & 1;
        const float cx = s_seeds[k][0], cy = s_seeds[k][1], cz = s_seeds[k][2];
        const uint64_t ncx2 = pack2(-cx, -cx);
        const uint64_t ncy2 = pack2(-cy, -cy);
        const uint64_t ncz2 = pack2(-cz, -cz);

        // ---- packed scan, dual max accumulators
        unsigned bd0 = 0, bd1 = 0;
#pragma unroll
        for (int j = 0; j < FPS_PR; j++) {
            const uint64_t ax = add2(PX[j], ncx2);
            const uint64_t ay = add2(PY[j], ncy2);
            const uint64_t az = add2(PZ[j], ncz2);
            const uint64_t dd = add2(add2(mul2(ax, ax), mul2(ay, ay)), mul2(az, az));
            float f0, f1; unpack2(dd, f0, f1);
            db[2 * j]     = min(db[2 * j],     __float_as_uint(f0));
            db[2 * j + 1] = min(db[2 * j + 1], __float_as_uint(f1));
            bd0 = max(bd0, db[2 * j]);
            bd1 = max(bd1, db[2 * j + 1]);
        }
        const unsigned bd = max(bd0, bd1);

        // ---- warp reduce: max dist, then first (min) gi among candidates
        const unsigned wbd = __reduce_max_sync(0xffffffffu, bd);
        unsigned mygi = 0xffffffffu;
        if (bd == wbd) {
#pragma unroll
            for (int i = 0; i < FPS_PT; i++)
                if (db[i] == wbd) mygi = min(mygi, (unsigned)(gi0 + i * FPS_T));
        }
        const unsigned wgi = __reduce_min_sync(0xffffffffu, mygi);
        if (lane == 0)
            s_wkey[warp] = ((uint64_t)wbd << 32) | (unsigned)(~wgi);
        __syncthreads();                  // ---- bar1

        if (warp == 0) {
            // block reduce over 8 warp keys (dual u32 REDUX)
            const uint64_t kk = (lane < FPS_T / 32) ? s_wkey[lane] : 0ull;
            const unsigned khi = (unsigned)(kk >> 32);
            const unsigned klo = (unsigned)kk;
            const unsigned hi = __reduce_max_sync(0xffffffffu, khi);
            const unsigned lo = __reduce_max_sync(0xffffffffu, (khi == hi) ? klo : 0u);
            const uint64_t ckey = ((uint64_t)hi << 32) | lo;

            // broadcast CTA key to all 8 CTAs' slots + arrive (parallel lanes)
            if (lane < FPS_CL) {
                const uint32_t slot_loc =
                    (uint32_t)__cvta_generic_to_shared(&s_slot[b][rank]);
                const uint32_t bar_loc =
                    (uint32_t)__cvta_generic_to_shared(&s_mbar[b]);
                st_cluster_b64(mapa_u32(slot_loc, (uint32_t)lane), ckey);
                mbar_arrive_rel_cluster(mapa_u32(bar_loc, (uint32_t)lane));
            }
            // all 32 lanes wait (converged)
            mbar_wait_acq_cluster((uint32_t)__cvta_generic_to_shared(&s_mbar[b]),
                                  (unsigned)((k >> 1) & 1));

            // cluster reduce over 8 slots
            const uint64_t sk = (lane < FPS_CL) ? s_slot[b][lane] : 0ull;
            const unsigned shi = (unsigned)(sk >> 32);
            const unsigned slo = (unsigned)sk;
            const unsigned hi2 = __reduce_max_sync(0xffffffffu, shi);
            const unsigned lo2 = __reduce_max_sync(0xffffffffu, (shi == hi2) ? slo : 0u);
            const unsigned widx = ~lo2;

            // winner xyz straight from global (L1/L2 hit), 3 lanes
            if (lane < 3)
                s_seeds[k + 1][lane] = base[(size_t)widx * 3 + lane];
        }
        __syncthreads();                  // ---- bar2
    }

    // =================== density tail ===================
    // NPN[j] = -( (x*x + y*y) + z*z ) per point pair (packed)
    const uint64_t signmask = 0x8000000080000000ull;
    uint64_t NPN[FPS_PR];
#pragma unroll
    for (int j = 0; j < FPS_PR; j++) {
        const uint64_t pn =
            add2(add2(mul2(PX[j], PX[j]), mul2(PY[j], PY[j])), mul2(PZ[j], PZ[j]));
        NPN[j] = pn ^ signmask;
    }

#pragma unroll 1
    for (int s = 0; s < NSEED; s++) {
        const float sx = s_seeds[s][0], sy = s_seeds[s][1], sz = s_seeds[s][2];
        const float qw = RAD2 - (sx * sx + sy * sy + sz * sz);
        const uint64_t qx2 = pack2(2.0f * sx, 2.0f * sx);
        const uint64_t qy2 = pack2(2.0f * sy, 2.0f * sy);
        const uint64_t qz2 = pack2(2.0f * sz, 2.0f * sz);
        const uint64_t qw2 = pack2(qw, qw);
        float acc = 0.0f;
#pragma unroll
        for (int j = 0; j < FPS_PR; j++) {
            uint64_t v = add2(qw2, NPN[j]);
            v = fma2(PX[j], qx2, v);
            v = fma2(PY[j], qy2, v);
            v = fma2(PZ[j], qz2, v);
            float v0, v1; unpack2(v, v0, v1);
            acc += fmaxf(v0, 0.0f);
            acc += fmaxf(v1, 0.0f);
        }
        s_part[s][t] = acc;
    }
    __syncthreads();

    if (t < NSEED) {
        const float* row = &s_part[t][0];
        float a0 = 0.f, a1 = 0.f, a2 = 0.f, a3 = 0.f;
#pragma unroll 4
        for (int i = 0; i < FPS_T; i += 4) {
            a0 += row[i]; a1 += row[i + 1]; a2 += row[i + 2]; a3 += row[i + 3];
        }
        atomicAdd(&g_den[batch * NSEED + t], (a0 + a1) + (a2 + a3));
    }
}

// ---------------------------------------------------------------------------
// Kernel 2: out = mean_b( var_{ddof=1,s}( den[b][s] ) )
// ---------------------------------------------------------------------------
__global__ void var_kernel(float* __restrict__ out)
{
    const int lane = threadIdx.x;
    float v = 0.0f;
    if (lane < NB) {
        const float* d = &g_den[lane * NSEED];
        float s = 0.0f;
        for (int i = 0; i < NSEED; i++) s += d[i];
        const float m = s * (1.0f / NSEED);
        float q = 0.0f;
        for (int i = 0; i < NSEED; i++) {
            const float e = d[i] - m;
            q += e * e;
        }
        v = q * (1.0f / (NSEED - 1));
    }
#pragma unroll
    for (int off = 8; off; off >>= 1)
        v += __shfl_down_sync(0xffffffffu, v, off);
    if (lane == 0) out[0] = v * (1.0f / NB);
}

// ---------------------------------------------------------------------------
extern "C" void kernel_launch(void* const* d_in, const int* in_sizes, int n_in,
                              void* d_out, int out_size)
{
    const float* pcs = (const float*)d_in[0];
    (void)in_sizes; (void)n_in; (void)out_size;

    fps_kernel<<<NB * FPS_CL, FPS_T>>>(pcs);
    var_kernel<<<1, 32>>>((float*)d_out);
}